// round 10
// baseline (speedup 1.0000x reference)
#include <cuda_runtime.h>
#include <cstdint>

// ---------------------------------------------------------------------------
// SpikingAttention: adaptive-LIF (LSNN) scans + WTA pseudo-softmax
// B=32, T=1000, D=512, U=512
// SERIAL phases (no GEMM/scan L2 interference):
//   1) transpose x -> g_xT
//   2) gemm_kernel: 3000 blocks x 256t, 8x8 f32x2/thread (full chip)
//   3) scan_kernel: 96 blocks x 512t (kqv | wta | att pipelined via flags;
//      W matrices stay L2-resident, I double-buffered in registers)
// ---------------------------------------------------------------------------

#define ALPHA 0.9f
#define RHO   0.995f
#define BETA  1.6f

#define NB 32
#define NT 1000
#define NU 512
#define MTOT (NB*NT)

#define OUT1_OFF 0ull
#define OUT2_OFF 16384000ull
#define OUT3_OFF 114688000ull
#define OUT4_OFF 180224000ull

__device__ float    g_xT[512ll * MTOT];          // x transposed: [k][t*32+b]
__device__ float    g_I[3ll * MTOT * NU];        // [pop][t*32+b][u]
__device__ unsigned g_spk[3ll * MTOT * 16];      // [pop][b][t][16]
__device__ unsigned g_zA[(long long)MTOT * 16];  // [b][t][16]
__device__ int      g_flag[64];                  // [0..31] kqv step, [32..63] zA step

// ---------------------------------------------------------------------------
__device__ __forceinline__ int ld_acquire(const int* p) {
    int v;
    asm volatile("ld.acquire.gpu.global.s32 %0, [%1];" : "=r"(v) : "l"(p) : "memory");
    return v;
}
__device__ __forceinline__ void st_release(int* p, int v) {
    asm volatile("st.release.gpu.global.s32 [%0], %1;" :: "l"(p), "r"(v) : "memory");
}
__device__ __forceinline__ void spin_ge(const int* p, int want) {
    while (ld_acquire(p) < want) { __nanosleep(60); }
}

#define FMA_F32X2(acc, a, b) \
    asm("fma.rn.f32x2 %0, %1, %2, %0;" : "+l"(acc) : "l"(a), "l"(b))
#define PACK_DUP2(out, f) \
    asm("mov.b64 %0, {%1, %1};" : "=l"(out) : "f"(f))

#define CP_ASYNC16(smem_addr, gptr) \
    asm volatile("cp.async.cg.shared.global [%0], [%1], 16;" :: "r"(smem_addr), "l"(gptr))
#define CP_COMMIT()  asm volatile("cp.async.commit_group;")
#define CP_WAIT(N)   asm volatile("cp.async.wait_group %0;" :: "n"(N))

__device__ __forceinline__ unsigned smem_u32(const void* p) {
    return (unsigned)__cvta_generic_to_shared(p);
}

// ---------------------------------------------------------------------------
// Transpose: x[b][t][k] -> xT[k][t*32+b]. grid (1000, 4), 256 threads.
// ---------------------------------------------------------------------------
__global__ __launch_bounds__(256) void transpose_kernel(const float* __restrict__ x)
{
    __shared__ float S[32][132];
    const int t  = blockIdx.x;
    const int kc = blockIdx.y;
    const int tid = threadIdx.x;
#pragma unroll
    for (int i = 0; i < 4; i++) {
        int f = i * 256 + tid;
        int b = f >> 5;
        int c4 = f & 31;
        float4 v = *(const float4*)(x + ((size_t)b * 1000 + t) * 512 + kc * 128 + c4 * 4);
        *(float4*)&S[b][c4 * 4] = v;
    }
    __syncthreads();
#pragma unroll
    for (int i = 0; i < 4; i++) {
        int f = i * 256 + tid;
        int kk = f >> 3;
        int c = f & 7;
        float4 v = make_float4(S[c * 4 + 0][kk], S[c * 4 + 1][kk],
                               S[c * 4 + 2][kk], S[c * 4 + 3][kk]);
        *(float4*)(g_xT + (size_t)(kc * 128 + kk) * MTOT + t * 32 + c * 4) = v;
    }
}

__global__ void reset_kernel()
{
    int i = threadIdx.x;
    if (i < 64) g_flag[i] = 0;
}

// ---------------------------------------------------------------------------
// GEMM: 3000 blocks x 256t, 128x128 tile, 8x8 f32x2/thread, 2-stage cp.async.
// g = mchunk*12 + pop*4 + nt
// ---------------------------------------------------------------------------
__global__ __launch_bounds__(256, 2) void gemm_kernel(
    const float* __restrict__ Wk,
    const float* __restrict__ Wq,
    const float* __restrict__ Wv)
{
    __shared__ float As[2][16][128];
    __shared__ float Bs[2][16][128];

    const int g = blockIdx.x;
    const int mchunk = g / 12;
    const int rem    = g % 12;
    const int pop    = rem >> 2;
    const int nt     = rem & 3;
    const float* __restrict__ W = (pop == 0) ? Wk : (pop == 1) ? Wq : Wv;
    float* __restrict__ C = g_I + (size_t)pop * MTOT * NU;

    const int tid = threadIdx.x;
    const int r0 = mchunk * 128;
    const int n0 = nt * 128;
    const int tx = tid & 15;
    const int ty = tid >> 4;
    const int noff = (tx & 3) * 32 + (tx >> 2) * 8;   // conflict-free B cols

    const float* srcA[2];
    const float* srcB[2];
    unsigned dstA[2][2], dstB[2][2];
#pragma unroll
    for (int l = 0; l < 2; l++) {
        int idx = l * 256 + tid;
        int kr = idx >> 5, sg = idx & 31;
        srcA[l] = g_xT + (size_t)kr * MTOT + r0 + sg * 4;
        srcB[l] = W + (size_t)kr * 512 + n0 + sg * 4;
#pragma unroll
        for (int s = 0; s < 2; s++) {
            dstA[s][l] = smem_u32(&As[s][kr][sg * 4]);
            dstB[s][l] = smem_u32(&Bs[s][kr][sg * 4]);
        }
    }

    unsigned long long acc[8][4];
#pragma unroll
    for (int i = 0; i < 8; i++)
#pragma unroll
        for (int j = 0; j < 4; j++) acc[i][j] = 0ull;

#pragma unroll
    for (int l = 0; l < 2; l++) {
        CP_ASYNC16(dstA[0][l], srcA[l]);
        CP_ASYNC16(dstB[0][l], srcB[l]);
    }
    CP_COMMIT();

    for (int kt = 0; kt < 32; kt++) {
        if (kt < 31) {
            const int k0 = (kt + 1) * 16;
            const int s = (kt + 1) & 1;
#pragma unroll
            for (int l = 0; l < 2; l++) {
                CP_ASYNC16(dstA[s][l], srcA[l] + (size_t)k0 * MTOT);
                CP_ASYNC16(dstB[s][l], srcB[l] + (size_t)k0 * 512);
            }
            CP_COMMIT();
            CP_WAIT(1);
        } else {
            CP_WAIT(0);
        }
        __syncthreads();

        const int s = kt & 1;
#pragma unroll
        for (int kk = 0; kk < 16; kk++) {
            float4 a0 = *(const float4*)&As[s][kk][ty * 8];
            float4 a1 = *(const float4*)&As[s][kk][ty * 8 + 4];
            ulonglong2 b01 = *(const ulonglong2*)&Bs[s][kk][noff];
            ulonglong2 b23 = *(const ulonglong2*)&Bs[s][kk][noff + 4];
            unsigned long long bp0 = b01.x, bp1 = b01.y, bp2 = b23.x, bp3 = b23.y;
            float av[8] = {a0.x, a0.y, a0.z, a0.w, a1.x, a1.y, a1.z, a1.w};
#pragma unroll
            for (int i = 0; i < 8; i++) {
                unsigned long long ad;
                PACK_DUP2(ad, av[i]);
                FMA_F32X2(acc[i][0], ad, bp0);
                FMA_F32X2(acc[i][1], ad, bp1);
                FMA_F32X2(acc[i][2], ad, bp2);
                FMA_F32X2(acc[i][3], ad, bp3);
            }
        }
        __syncthreads();
    }

#pragma unroll
    for (int i = 0; i < 8; i++) {
        float* Crow = C + (size_t)(r0 + ty * 8 + i) * 512 + n0 + noff;
        ulonglong2 v0; v0.x = acc[i][0]; v0.y = acc[i][1];
        ulonglong2 v1; v1.x = acc[i][2]; v1.y = acc[i][3];
        *(ulonglong2*)Crow = v0;
        *((ulonglong2*)Crow + 1) = v1;
    }
}

// ---------------------------------------------------------------------------
struct ScanSmem {
    unsigned mask[3][16];
    unsigned maskZ[16];
    unsigned maskR[16];
    float red[16];
    int totK, totQ, totV, totKQ, totAtt;
    unsigned short listK[528], listQ[528], listV[528];
    unsigned short listKQ[1056];
    unsigned short listAtt[1584];
};

__device__ __forceinline__ int build_list(unsigned m, int bias,
                                          unsigned short* list, int list_off)
{
    const int lane = threadIdx.x & 31;
    int c = __popc(m);
    int inc = c;
#pragma unroll
    for (int o = 1; o < 32; o <<= 1) {
        int v = __shfl_up_sync(0xffffffffu, inc, o);
        if (lane >= o) inc += v;
    }
    int off  = list_off + inc - c;
    int base = bias + lane * 32;
    while (m) {
        int j = __ffs((int)m) - 1;
        list[off++] = (unsigned short)(base + j);
        m &= (m - 1);
    }
    return __shfl_sync(0xffffffffu, inc, 31);
}

__device__ __forceinline__ float gather16(const float* __restrict__ W,
                                          const unsigned short* list, int n,
                                          int u, float acc)
{
    for (int i = 0; i < n; i += 16) {
        float w[16];
#pragma unroll
        for (int k = 0; k < 16; k++) {
            int j = list[i + k];
            w[k] = W[(size_t)j * 512 + u];
        }
#pragma unroll
        for (int k = 0; k < 16; k++)
            if (i + k < n) acc += w[k];
    }
    return acc;
}

__device__ __forceinline__ float gather16_2(const float* __restrict__ Win,
                                            const float* __restrict__ Wrec,
                                            const unsigned short* list, int n,
                                            int u, float acc)
{
    for (int i = 0; i < n; i += 16) {
        float w[16];
#pragma unroll
        for (int k = 0; k < 16; k++) {
            int j = list[i + k];
            const float* base = (j < 1024) ? (Win + (size_t)j * 512)
                                           : (Wrec + (size_t)(j - 1024) * 512);
            w[k] = base[u];
        }
#pragma unroll
        for (int k = 0; k < 16; k++)
            if (i + k < n) acc += w[k];
    }
    return acc;
}

// ---------------------------------------------------------------------------
// kqv role: 512t, 1 neuron/thread, k/q/v interleaved. I double-buffered in
// registers (t+1 loads issue at step start -> latency hidden). 2 bars/step.
// ---------------------------------------------------------------------------
__device__ void kqv_role(int b,
                         const float* __restrict__ WkR,
                         const float* __restrict__ WqR,
                         const float* __restrict__ WvR,
                         float* __restrict__ d_out, ScanSmem* ss)
{
    const float* __restrict__ Ik = g_I + (size_t)0 * MTOT * NU;
    const float* __restrict__ Iq = g_I + (size_t)1 * MTOT * NU;
    const float* __restrict__ Iv = g_I + (size_t)2 * MTOT * NU;

    unsigned* __restrict__ spkK = g_spk + ((size_t)0 * NB + b) * NT * 16;
    unsigned* __restrict__ spkQ = g_spk + ((size_t)1 * NB + b) * NT * 16;
    unsigned* __restrict__ spkV = g_spk + ((size_t)2 * NB + b) * NT * 16;

    float* __restrict__ out2 = d_out + OUT2_OFF;
    float* __restrict__ out3 = d_out + OUT3_OFF;
    float* __restrict__ out4 = d_out + OUT4_OFF;

    const int tid = threadIdx.x, u = tid, warp = tid >> 5, lane = tid & 31;

    if (tid < 16) {
        ss->mask[0][tid] = 0u; ss->mask[1][tid] = 0u; ss->mask[2][tid] = 0u;
    }
    __syncthreads();

    float vK = 0.f, aK = 0.f, zK = 0.f;
    float vQ = 0.f, aQ = 0.f, zQ = 0.f;
    float vV = 0.f, aV = 0.f, zV = 0.f;

    // preload I for t=0
    float IK = Ik[(size_t)b * 512 + u];
    float IQ = Iq[(size_t)b * 512 + u];
    float IV = Iv[(size_t)b * 512 + u];

    for (int t = 0; t < NT; t++) {
        // issue next-step I loads (hidden behind this step's work)
        const int tn = (t + 1 < NT) ? t + 1 : t;
        const size_t ioff = ((size_t)tn * 32 + b) * 512 + u;
        float nIK = Ik[ioff];
        float nIQ = Iq[ioff];
        float nIV = Iv[ioff];

        if (warp == 0) {
            int tot = build_list(lane < 16 ? ss->mask[0][lane] : 0u, 0, ss->listK, 0);
            if (lane < 16) ss->listK[tot + lane] = 0;
            if (lane == 0) ss->totK = tot;
        } else if (warp == 1) {
            int tot = build_list(lane < 16 ? ss->mask[1][lane] : 0u, 0, ss->listQ, 0);
            if (lane < 16) ss->listQ[tot + lane] = 0;
            if (lane == 0) ss->totQ = tot;
        } else if (warp == 2) {
            int tot = build_list(lane < 16 ? ss->mask[2][lane] : 0u, 0, ss->listV, 0);
            if (lane < 16) ss->listV[tot + lane] = 0;
            if (lane == 0) ss->totV = tot;
        }
        __syncthreads();                                    // B1

        const int nK = ss->totK, nQ = ss->totQ, nV = ss->totV;
        float accK = IK, accQ = IQ, accV = IV;
        {
            int nmax = nK > nQ ? nK : nQ;
            if (nV > nmax) nmax = nV;
            for (int i = 0; i < nmax; i += 8) {
                float wk[8], wq[8], wv[8];
                const bool dk = i < nK, dq = i < nQ, dv = i < nV;
#pragma unroll
                for (int k2 = 0; k2 < 8; k2++) {
                    if (dk) wk[k2] = WkR[(size_t)ss->listK[i + k2] * 512 + u];
                    if (dq) wq[k2] = WqR[(size_t)ss->listQ[i + k2] * 512 + u];
                    if (dv) wv[k2] = WvR[(size_t)ss->listV[i + k2] * 512 + u];
                }
#pragma unroll
                for (int k2 = 0; k2 < 8; k2++) {
                    if (i + k2 < nK) accK += wk[k2];
                    if (i + k2 < nQ) accQ += wq[k2];
                    if (i + k2 < nV) accV += wv[k2];
                }
            }
        }

        float aKn = RHO * aK + zK, thrK = 1.0f + BETA * aKn;
        float vKn = ALPHA * vK + accK - zK * thrK, vscK = vKn - thrK;
        float zKn = (vscK > 0.f) ? 1.f : 0.f;
        float aQn = RHO * aQ + zQ, thrQ = 1.0f + BETA * aQn;
        float vQn = ALPHA * vQ + accQ - zQ * thrQ, vscQ = vQn - thrQ;
        float zQn = (vscQ > 0.f) ? 1.f : 0.f;
        float aVn = RHO * aV + zV, thrV = 1.0f + BETA * aVn;
        float vVn = ALPHA * vV + accV - zV * thrV, vscV = vVn - thrV;
        float zVn = (vscV > 0.f) ? 1.f : 0.f;

        unsigned balK = __ballot_sync(0xffffffffu, zKn > 0.f);
        unsigned balQ = __ballot_sync(0xffffffffu, zQn > 0.f);
        unsigned balV = __ballot_sync(0xffffffffu, zVn > 0.f);
        if (lane == 0) {
            ss->mask[0][warp] = balK;
            ss->mask[1][warp] = balQ;
            ss->mask[2][warp] = balV;
            spkK[(size_t)t * 16 + warp] = balK;
            spkQ[(size_t)t * 16 + warp] = balQ;
            spkV[(size_t)t * 16 + warp] = balV;
        }
        __syncthreads();                                    // B2
        if (tid == 0) st_release(&g_flag[b], t + 1);

        const size_t base = (size_t)b * NT + t;
        __stcs(&out2[base * 3072 + 0 * 512 + u], zKn);
        __stcs(&out2[base * 3072 + 1 * 512 + u], zQn);
        __stcs(&out2[base * 3072 + 2 * 512 + u], zVn);
        __stcs(&out3[base * 2048 + 0 * 512 + u], thrK);
        __stcs(&out3[base * 2048 + 1 * 512 + u], thrQ);
        __stcs(&out3[base * 2048 + 2 * 512 + u], thrV);
        __stcs(&out4[base * 3072 + 0 * 512 + u], vscK);
        __stcs(&out4[base * 3072 + 1 * 512 + u], vscQ);
        __stcs(&out4[base * 3072 + 2 * 512 + u], vscV);

        vK = vKn; aK = aKn; zK = zKn;
        vQ = vQn; aQ = aQn; zQ = zQn;
        vV = vVn; aV = aVn; zV = zVn;
        IK = nIK; IQ = nIQ; IV = nIV;
    }
}

// ---------------------------------------------------------------------------
// WTA role: 512t. 4 bars/step.
// ---------------------------------------------------------------------------
__device__ void wta_role(int b, const float* __restrict__ Wa,
                         const float* __restrict__ Wb,
                         float* __restrict__ d_out, ScanSmem* ss)
{
    const unsigned* __restrict__ spkK = g_spk + (size_t)b * NT * 16;
    const unsigned* __restrict__ spkQ = g_spk + ((size_t)NB + b) * NT * 16;
    unsigned* __restrict__ zAout      = g_zA + (size_t)b * NT * 16;

    float* __restrict__ out2 = d_out + OUT2_OFF;
    float* __restrict__ out4 = d_out + OUT4_OFF;

    const int tid = threadIdx.x, u = tid, warp = tid >> 5, lane = tid & 31;

    float vA = 0.f, vB = 0.f, zA = 0.f, zB = 0.f;

    for (int t = 0; t < NT; t++) {
        if (warp == 0) {
            if (lane == 0) spin_ge(&g_flag[b], t + 1);
            __syncwarp();
            unsigned m = (lane < 16) ? __ldcg(&spkK[(size_t)t * 16 + lane])
                                     : __ldcg(&spkQ[(size_t)t * 16 + (lane - 16)]);
            int tot = build_list(m, 0, ss->listKQ, 0);
            if (lane < 16) ss->listKQ[tot + lane] = 0;
            if (lane == 0) ss->totKQ = tot;
        }
        __syncthreads();                                   // B1
        const int nsp = ss->totKQ;

        float acc = gather16(Wa, ss->listKQ, nsp, u, 0.f);

        float vAn = ALPHA * vA + acc - zA;
        float vscA = vAn - 1.0f;

        float mx = vAn;
#pragma unroll
        for (int o = 16; o > 0; o >>= 1) mx = fmaxf(mx, __shfl_xor_sync(0xffffffffu, mx, o));
        if (lane == 0) ss->red[warp] = mx;
        __syncthreads();                                   // B2
        float mm = ss->red[lane & 15];
#pragma unroll
        for (int o = 8; o > 0; o >>= 1) mm = fmaxf(mm, __shfl_xor_sync(0xffffffffu, mm, o));

        float winner = (vAn == mm) ? 1.f : 0.f;
        float zAn = (vscA > 0.f) ? winner : 0.f;

        unsigned balZ = __ballot_sync(0xffffffffu, zAn > 0.f);
        if (lane == 0) {
            ss->maskZ[warp] = balZ;
            zAout[(size_t)t * 16 + warp] = balZ;
        }
        __syncthreads();                                   // B3
        if (tid == 0) st_release(&g_flag[32 + b], t + 1);

        float accB = 0.f;
#pragma unroll
        for (int w = 0; w < 16; w++) {
            unsigned mb = ss->maskZ[w];
            while (mb) {
                int j = __ffs((int)mb) - 1;
                accB += Wb[(size_t)(w * 32 + j) * 512 + u];
                mb &= mb - 1;
            }
        }
        float vBn = ALPHA * vB + accB - zB;
        float vscB = vBn - 1.0f;
        float zBn = (vscB > 0.f) ? 1.f : 0.f;

        const size_t base = (size_t)b * NT + t;
        __stcs(&out2[base * 3072 + 3 * 512 + u], zAn);
        __stcs(&out2[base * 3072 + 4 * 512 + u], zBn);
        __stcs(&out4[base * 3072 + 3 * 512 + u], vscA);
        __stcs(&out4[base * 3072 + 4 * 512 + u], vscB);

        vA = vAn; vB = vBn; zA = zAn; zB = zBn;
        __syncthreads();                                   // B4
    }
}

// ---------------------------------------------------------------------------
// Attention LSNN role: 512t. 2 bars/step.
// ---------------------------------------------------------------------------
__device__ void att_role(int b, const float* __restrict__ Win,
                         const float* __restrict__ Wrec,
                         float* __restrict__ d_out, ScanSmem* ss)
{
    const unsigned* __restrict__ spkV = g_spk + ((size_t)2 * NB + b) * NT * 16;
    const unsigned* __restrict__ zAin = g_zA + (size_t)b * NT * 16;

    float* __restrict__ out1 = d_out + OUT1_OFF;
    float* __restrict__ out2 = d_out + OUT2_OFF;
    float* __restrict__ out3 = d_out + OUT3_OFF;
    float* __restrict__ out4 = d_out + OUT4_OFF;

    const int tid = threadIdx.x, u = tid, warp = tid >> 5, lane = tid & 31;

    if (tid < 16) ss->maskR[tid] = 0u;
    __syncthreads();

    float v = 0.f, a = 0.f, z = 0.f;

    for (int t = 0; t < NT; t++) {
        if (warp == 0) {
            if (lane == 0) spin_ge(&g_flag[b], t + 1);
            if (lane == 1) spin_ge(&g_flag[32 + b], t + 1);
            __syncwarp();
            unsigned m1 = (lane < 16) ? __ldcg(&spkV[(size_t)t * 16 + lane])
                                      : __ldcg(&zAin[(size_t)t * 16 + (lane - 16)]);
            int t1 = build_list(m1, 0, ss->listAtt, 0);
            unsigned m2 = (lane < 16) ? ss->maskR[lane] : 0u;
            int t2 = build_list(m2, 1024, ss->listAtt, t1);
            int tot = t1 + t2;
            if (lane < 16) ss->listAtt[tot + lane] = 0;
            if (lane == 0) ss->totAtt = tot;
        }
        __syncthreads();                                   // B1
        const int nsp = ss->totAtt;

        float acc = gather16_2(Win, Wrec, ss->listAtt, nsp, u, 0.f);

        float an = RHO * a + z, thr = 1.0f + BETA * an;
        float vn = ALPHA * v + acc - z * thr, vsc = vn - thr;
        float zn = (vsc > 0.f) ? 1.f : 0.f;

        unsigned bal = __ballot_sync(0xffffffffu, zn > 0.f);
        if (lane == 0) ss->maskR[warp] = bal;

        const size_t base = (size_t)b * NT + t;
        __stcs(&out1[base * 512 + u], zn);
        __stcs(&out2[base * 3072 + 5 * 512 + u], zn);
        __stcs(&out3[base * 2048 + 3 * 512 + u], thr);
        __stcs(&out4[base * 3072 + 5 * 512 + u], vsc);

        v = vn; a = an; z = zn;
        __syncthreads();                                   // B2
    }
}

// ---------------------------------------------------------------------------
__global__ __launch_bounds__(512, 2) void scan_kernel(
    const float* __restrict__ Wk_rec, const float* __restrict__ Wq_rec,
    const float* __restrict__ Wv_rec,
    const float* __restrict__ Watt_in, const float* __restrict__ Watt_rec,
    const float* __restrict__ Wwta_a, const float* __restrict__ Wwta_b,
    float* __restrict__ d_out)
{
    __shared__ __align__(16) unsigned char smem_raw[sizeof(ScanSmem)];
    ScanSmem* ss = (ScanSmem*)smem_raw;
    const int bid = blockIdx.x;
    if (bid < 32) {
        kqv_role(bid, Wk_rec, Wq_rec, Wv_rec, d_out, ss);
    } else if (bid < 64) {
        wta_role(bid - 32, Wwta_a, Wwta_b, d_out, ss);
    } else {
        att_role(bid - 64, Watt_in, Watt_rec, d_out, ss);
    }
}

// ---------------------------------------------------------------------------
extern "C" void kernel_launch(void* const* d_in, const int* in_sizes, int n_in,
                              void* d_out, int out_size)
{
    const float* x        = (const float*)d_in[0];
    const float* Wk_in    = (const float*)d_in[1];
    const float* Wk_rec   = (const float*)d_in[2];
    const float* Wq_in    = (const float*)d_in[3];
    const float* Wq_rec   = (const float*)d_in[4];
    const float* Wv_in    = (const float*)d_in[5];
    const float* Wv_rec   = (const float*)d_in[6];
    const float* Watt_in  = (const float*)d_in[7];
    const float* Watt_rec = (const float*)d_in[8];
    const float* Wwta_a   = (const float*)d_in[9];
    const float* Wwta_b   = (const float*)d_in[10];
    float* out = (float*)d_out;

    (void)in_sizes; (void)n_in; (void)out_size;

    dim3 gT(1000, 4);
    transpose_kernel<<<gT, 256>>>(x);
    reset_kernel<<<1, 64>>>();
    gemm_kernel<<<3000, 256>>>(Wk_in, Wq_in, Wv_in);
    scan_kernel<<<96, 512>>>(Wk_rec, Wq_rec, Wv_rec, Watt_in, Watt_rec,
                             Wwta_a, Wwta_b, out);
}